// round 3
// baseline (speedup 1.0000x reference)
#include <cuda_runtime.h>
#include <cuda_bf16.h>
#include <math.h>

#define H 256
#define E_MAX 500000
#define G_MAX 512
#define EPS_F 1.1920928955078125e-07f
#define GPB 4

// ---------------- scratch (static device globals; no allocation) -------------
__device__ float d_att_raw[E_MAX];
__device__ float d_v[H];          // att_vec @ W_edge
__device__ float d_qscore[G_MAX]; // question_tokens[g] . (att_vec @ W_query)
__device__ int   d_gmax[G_MAX];   // encoded float max per graph
__device__ float d_gsum[G_MAX];
__device__ int   d_gcount[G_MAX];
__device__ float d_pooled[G_MAX * H]; // segment_sum of RAW edge_tokens

// order-preserving float<->int encode for atomicMax
__device__ __forceinline__ int fenc(float f) {
    int i = __float_as_int(f);
    return i < 0 ? (i ^ 0x7FFFFFFF) : i;
}
__device__ __forceinline__ float fdec(int i) {
    return __int_as_float(i < 0 ? (i ^ 0x7FFFFFFF) : i);
}

// ---------------- init ------------------------------------------------------
__global__ void k_init(int G) {
    int i = blockIdx.x * blockDim.x + threadIdx.x;
    if (i < G * H) d_pooled[i] = 0.f;
    if (i < G) {
        d_gsum[i] = 0.f;
        d_gcount[i] = 0;
        d_gmax[i] = 0x80000000; // < any encoded float
    }
}

// ---------------- K0: v, w, qscore -----------------------------------------
__global__ void k0_precompute(const float* __restrict__ qt,
                              const float* __restrict__ We,
                              const float* __restrict__ Wq,
                              const float* __restrict__ av, int G) {
    __shared__ float s_att[H];
    __shared__ float s_w[H];
    int t = threadIdx.x;
    s_att[t] = av[t];
    __syncthreads();
    float v = 0.f, w = 0.f;
#pragma unroll 8
    for (int i = 0; i < H; i++) {
        float a = s_att[i];
        v += a * We[i * H + t]; // W_edge[i][t]
        w += a * Wq[i * H + t];
    }
    d_v[t] = v;
    s_w[t] = w;
    __syncthreads();
    for (int g = t; g < G; g += blockDim.x) {
        const float* qr = qt + (size_t)g * H;
        float q = 0.f;
#pragma unroll 8
        for (int h = 0; h < H; h++) q += qr[h] * s_w[h];
        d_qscore[g] = q;
    }
}

// ---------------- K1: heavy streaming pass over edge_tokens ------------------
// warp-per-edge, prefetch depth 2: lane covers h = lane*8..lane*8+7
__global__ void __launch_bounds__(512, 2)
k1_stream(const float* __restrict__ et,
          const int* __restrict__ eb,
          const int* __restrict__ sel, int E) {
    const int lane = threadIdx.x & 31;
    const int wid = blockIdx.x * (blockDim.x >> 5) + (threadIdx.x >> 5);
    const int nw = gridDim.x * (blockDim.x >> 5);
    const int chunk = (E + nw - 1) / nw;
    int e0 = wid * chunk;
    int e1 = min(e0 + chunk, E);
    if (e0 >= e1) return;

    float vr[8];
#pragma unroll
    for (int i = 0; i < 8; i++) vr[i] = d_v[lane * 8 + i];

    float acc[8];
#pragma unroll
    for (int i = 0; i < 8; i++) acc[i] = 0.f;
    float wmax = -3.402823466e38f;
    int wcnt = 0;
    int cur = eb[e0];

    const float4* row = reinterpret_cast<const float4*>(et);
    const int last = e1 - 1;
    // pipeline: x = row e, y = row e+1 (clamped)
    size_t b0 = (size_t)e0 * (H / 4) + lane * 2;
    float4 x0 = row[b0], x1 = row[b0 + 1];
    size_t b1i = (size_t)min(e0 + 1, last) * (H / 4) + lane * 2;
    float4 y0 = row[b1i], y1 = row[b1i + 1];

    for (int e = e0; e < e1; ++e) {
        // prefetch e+2 (clamped to a valid row; duplicate loads hit L1/L2)
        size_t nb = (size_t)min(e + 2, last) * (H / 4) + lane * 2;
        float4 z0 = row[nb], z1 = row[nb + 1];

        int b = eb[e];
        if (b != cur) {
            // flush per-graph state (rare: ~1-2 per warp)
#pragma unroll
            for (int i = 0; i < 8; i++) {
                atomicAdd(&d_pooled[cur * H + lane * 8 + i], acc[i]);
                acc[i] = 0.f;
            }
            if (lane == 0) {
                atomicMax(&d_gmax[cur], fenc(wmax));
                atomicAdd(&d_gcount[cur], wcnt);
            }
            wmax = -3.402823466e38f;
            wcnt = 0;
            cur = b;
        }
        acc[0] += x0.x; acc[1] += x0.y; acc[2] += x0.z; acc[3] += x0.w;
        acc[4] += x1.x; acc[5] += x1.y; acc[6] += x1.z; acc[7] += x1.w;
        float p = x0.x * vr[0] + x0.y * vr[1] + x0.z * vr[2] + x0.w * vr[3]
                + x1.x * vr[4] + x1.y * vr[5] + x1.z * vr[6] + x1.w * vr[7];
#pragma unroll
        for (int o = 16; o > 0; o >>= 1) p += __shfl_xor_sync(0xffffffffu, p, o);
        if (lane == 0) {
            float a = p + d_qscore[b];
            a = a > 0.f ? a : 0.2f * a;        // LeakyReLU(0.2)
            if (sel[e] == 0) a += 0.5f;        // frontier bonus (candidates)
            d_att_raw[e] = a;
            wmax = fmaxf(wmax, a);
            wcnt++;
        }
        x0 = y0; x1 = y1;
        y0 = z0; y1 = z1;
    }
    // final flush
#pragma unroll
    for (int i = 0; i < 8; i++) atomicAdd(&d_pooled[cur * H + lane * 8 + i], acc[i]);
    if (lane == 0) {
        atomicMax(&d_gmax[cur], fenc(wmax));
        atomicAdd(&d_gcount[cur], wcnt);
    }
}

// ---------------- K2: per-graph exp-sum (warp-segmented before L2) ----------
__global__ void k2_expsum(const int* __restrict__ eb,
                          const int* __restrict__ sel, int E) {
    int e = blockIdx.x * blockDim.x + threadIdx.x;
    int lane = threadIdx.x & 31;
    int b = -1;
    float val = 0.f;
    if (e < E) {
        b = eb[e];
        if (sel[e] == 0) {
            float m = fdec(d_gmax[b]);
            val = expf(d_att_raw[e] - m);
        }
    }
    // segmented warp reduction: edge_batch is sorted, so a warp spans few segs
    unsigned mask = 0xffffffffu;
#pragma unroll
    for (int o = 1; o < 32; o <<= 1) {
        float ov = __shfl_down_sync(mask, val, o);
        int   ob = __shfl_down_sync(mask, b, o);
        if (lane + o < 32 && ob == b) val += ov;
    }
    int bprev = __shfl_up_sync(mask, b, 1);
    bool head = (lane == 0) || (bprev != b);
    if (head && b >= 0 && val != 0.f) atomicAdd(&d_gsum[b], val);
}

// ---------------- K3: edge logits -------------------------------------------
__global__ void k3_logits(const int* __restrict__ eb,
                          const int* __restrict__ sel, int E,
                          float* __restrict__ out_edge) {
    int e = blockIdx.x * blockDim.x + threadIdx.x;
    if (e >= E) return;
    int b = eb[e];
    float p = 0.f;
    if (sel[e] == 0) {
        float m = fdec(d_gmax[b]);
        float S = fmaxf(d_gsum[b], EPS_F);
        p = expf(d_att_raw[e] - m) / S;
    }
    out_edge[e] = logf(fmaxf(p, EPS_F));
}

// ---------------- K4: pooled GEMM + stop head (4 graphs / block) -------------
__device__ __forceinline__ float blockSum(float v) {
    __shared__ float sb[8];
    int lane = threadIdx.x & 31;
    int w = threadIdx.x >> 5;
#pragma unroll
    for (int o = 16; o > 0; o >>= 1) v += __shfl_xor_sync(0xffffffffu, v, o);
    if (lane == 0) sb[w] = v;
    __syncthreads();
    if (w == 0) {
        float t = (lane < 8) ? sb[lane] : 0.f;
#pragma unroll
        for (int o = 4; o > 0; o >>= 1) t += __shfl_xor_sync(0xffffffffu, t, o);
        if (lane == 0) sb[0] = t;
    }
    __syncthreads();
    float r = sb[0];
    __syncthreads();
    return r;
}

__global__ void k4_head(const float* __restrict__ qt,
                        const float* __restrict__ We,
                        const float* __restrict__ lng,
                        const float* __restrict__ lnb,
                        const float* __restrict__ W1,
                        const float* __restrict__ b1,
                        const float* __restrict__ W2,
                        const float* __restrict__ b2,
                        float* __restrict__ out_stop,
                        float* __restrict__ out_pooled, int G) {
    __shared__ float sS[GPB][H];
    __shared__ float sIn[GPB][2 * H];
    __shared__ float sXn[GPB][2 * H];
    int t = threadIdx.x;
    int g0 = blockIdx.x * GPB;

    float inv_den[GPB];
#pragma unroll
    for (int gg = 0; gg < GPB; gg++) {
        int g = g0 + gg;
        sS[gg][t] = (g < G) ? d_pooled[g * H + t] : 0.f;
        inv_den[gg] = (g < G) ? 1.f / (float)max(d_gcount[g], 1) : 0.f;
    }
    __syncthreads();

    // pooled_edges[g][t] = (sum_tokens[g] @ W_edge.T)[t] / denom
    float pv[GPB] = {0.f, 0.f, 0.f, 0.f};
    for (int j = 0; j < H; j++) {
        float wv = We[t * H + j]; // W_edge[t][j]
#pragma unroll
        for (int gg = 0; gg < GPB; gg++) pv[gg] += sS[gg][j] * wv;
    }
#pragma unroll
    for (int gg = 0; gg < GPB; gg++) {
        int g = g0 + gg;
        float pooled = pv[gg] * inv_den[gg];
        sIn[gg][t] = pooled;
        sIn[gg][t + H] = (g < G) ? qt[(size_t)g * H + t] : 0.f;
        if (g < G) out_pooled[(size_t)g * H + t] = pooled;
    }
    __syncthreads();

    // LayerNorm(2H)
#pragma unroll
    for (int gg = 0; gg < GPB; gg++) {
        float a = sIn[gg][t], b = sIn[gg][t + H];
        float mu = blockSum(a + b) * (1.f / (2.f * H));
        float d0 = a - mu, d1 = b - mu;
        float var = blockSum(d0 * d0 + d1 * d1) * (1.f / (2.f * H));
        float rs = rsqrtf(var + 1e-5f);
        sXn[gg][t] = d0 * rs * lng[t] + lnb[t];
        sXn[gg][t + H] = d1 * rs * lng[t + H] + lnb[t + H];
    }
    __syncthreads();

    // h1 = gelu(xn @ W1.T + b1);  stop = h1 @ W2 + b2
    float hv[GPB];
    float b1t = b1[t];
#pragma unroll
    for (int gg = 0; gg < GPB; gg++) hv[gg] = b1t;
    for (int k = 0; k < 2 * H; k++) {
        float w1v = W1[t * (2 * H) + k]; // W1[t][k]
#pragma unroll
        for (int gg = 0; gg < GPB; gg++) hv[gg] += sXn[gg][k] * w1v;
    }
    float w2 = W2[t];
#pragma unroll
    for (int gg = 0; gg < GPB; gg++) {
        float h = hv[gg];
        h = h * normcdff(h); // exact GELU: x * Phi(x)
        float s = blockSum(h * w2);
        int g = g0 + gg;
        if (t == 0 && g < G) out_stop[g] = s + b2[0];
    }
}

// ---------------- launch -----------------------------------------------------
extern "C" void kernel_launch(void* const* d_in, const int* in_sizes, int n_in,
                              void* d_out, int out_size) {
    const float* et  = (const float*)d_in[0];   // edge_tokens   [E,H]
    const float* qt  = (const float*)d_in[1];   // question_tokens [G,H]
    const int*   eb  = (const int*)d_in[2];     // edge_batch    [E]
    const int*   sel = (const int*)d_in[3];     // selected_mask [E]
    const float* We  = (const float*)d_in[4];   // W_edge [H,H]
    const float* Wq  = (const float*)d_in[5];   // W_query [H,H]
    const float* av  = (const float*)d_in[6];   // att_vec [H]
    const float* lng = (const float*)d_in[7];   // ln_g [2H]
    const float* lnb = (const float*)d_in[8];   // ln_b [2H]
    const float* W1  = (const float*)d_in[9];   // [H,2H]
    const float* b1  = (const float*)d_in[10];  // [H]
    const float* W2  = (const float*)d_in[11];  // [1,H]
    const float* b2  = (const float*)d_in[12];  // [1]

    int E = in_sizes[2];
    int G = in_sizes[1] / H;
    float* out = (float*)d_out;
    float* out_edge   = out;          // [E]
    float* out_stop   = out + E;      // [G]
    float* out_pooled = out + E + G;  // [G,H]

    k_init<<<(G * H + 255) / 256, 256>>>(G);
    k0_precompute<<<1, 256>>>(qt, We, Wq, av, G);
    k1_stream<<<296, 512>>>(et, eb, sel, E);
    k2_expsum<<<(E + 255) / 256, 256>>>(eb, sel, E);
    k3_logits<<<(E + 255) / 256, 256>>>(eb, sel, E, out_edge);
    k4_head<<<(G + GPB - 1) / GPB, 256>>>(qt, We, lng, lnb, W1, b1, W2, b2,
                                          out_stop, out_pooled, G);
}

// round 5
// speedup vs baseline: 1.2371x; 1.2371x over previous
#include <cuda_runtime.h>
#include <cuda_bf16.h>
#include <math.h>

#define H 256
#define E_MAX 500000
#define G_MAX 512
#define EPS_F 1.1920928955078125e-07f
#define GPB 2

// ---------------- scratch (static device globals) ----------------------------
__device__ float d_att_raw[E_MAX];
__device__ float d_v[H];              // att_vec @ W_edge
__device__ float d_qscore[G_MAX];     // q[g] . (att_vec @ W_query)
__device__ float d_pooled[G_MAX * H]; // segment_sum of RAW edge_tokens
__device__ int   d_bounds[G_MAX + 1]; // segment boundaries in sorted eb

// ---------------- init: zero pooled sums ------------------------------------
__global__ void k_init(int G) {
    int i = blockIdx.x * blockDim.x + threadIdx.x;
    if (i < G * H) d_pooled[i] = 0.f;
}

// ---------------- bounds: lower_bound(eb, g) for each g ----------------------
__global__ void k_bounds(const int* __restrict__ eb, int E, int G) {
    int g = blockIdx.x * blockDim.x + threadIdx.x;
    if (g > G) return;
    if (g == G) { d_bounds[G] = E; return; }
    int lo = 0, hi = E;
    while (lo < hi) {
        int mid = (lo + hi) >> 1;
        if (eb[mid] < g) lo = mid + 1; else hi = mid;
    }
    d_bounds[g] = lo;
}

// ---------------- K0: v, w, qscore -------------------------------------------
__global__ void k0_precompute(const float* __restrict__ qt,
                              const float* __restrict__ We,
                              const float* __restrict__ Wq,
                              const float* __restrict__ av, int G) {
    __shared__ float s_att[H];
    __shared__ float s_w[H];
    int t = threadIdx.x;
    s_att[t] = av[t];
    __syncthreads();
    float v = 0.f, w = 0.f;
#pragma unroll 8
    for (int i = 0; i < H; i++) {
        float a = s_att[i];
        v += a * We[i * H + t];
        w += a * Wq[i * H + t];
    }
    d_v[t] = v;
    s_w[t] = w;
    __syncthreads();
    for (int g = t; g < G; g += blockDim.x) {
        const float* qr = qt + (size_t)g * H;
        float q = 0.f;
#pragma unroll 8
        for (int h = 0; h < H; h++) q += qr[h] * s_w[h];
        d_qscore[g] = q;
    }
}

// ---------------- K1: heavy streaming pass, 4 edges per iteration ------------
// lane covers h = lane*8 .. lane*8+7 (two float4 per row)
// __launch_bounds__(256,2): 128-reg budget -> no spills; 16 warps/SM is ample
// latency coverage (64KB outstanding/SM vs ~25KB needed for LTS share)
__global__ void __launch_bounds__(256, 2)
k1_stream(const float* __restrict__ et,
          const int* __restrict__ eb,
          const int* __restrict__ sel, int E) {
    const int lane = threadIdx.x & 31;
    const int wid = blockIdx.x * (blockDim.x >> 5) + (threadIdx.x >> 5);
    const int nw = gridDim.x * (blockDim.x >> 5);
    const int chunk = (E + nw - 1) / nw;
    int e0 = wid * chunk;
    int e1 = min(e0 + chunk, E);
    if (e0 >= e1) return;

    float vr[8];
#pragma unroll
    for (int i = 0; i < 8; i++) vr[i] = d_v[lane * 8 + i];
    float acc[8];
#pragma unroll
    for (int i = 0; i < 8; i++) acc[i] = 0.f;
    int cur = eb[e0];

    const float4* row = reinterpret_cast<const float4*>(et);
    int e = e0;

    for (; e + 4 <= e1; e += 4) {
        // batch-issue 8 wide loads (4 rows) -> high MLP
        float4 r[8];
        size_t base = (size_t)e * (H / 4) + lane * 2;
#pragma unroll
        for (int k = 0; k < 4; k++) {
            r[2 * k]     = row[base + (size_t)k * (H / 4)];
            r[2 * k + 1] = row[base + (size_t)k * (H / 4) + 1];
        }
        int b4[4];
#pragma unroll
        for (int k = 0; k < 4; k++) b4[k] = eb[e + k];

        float dots[4];
#pragma unroll
        for (int k = 0; k < 4; k++) {
            if (b4[k] != cur) {
#pragma unroll
                for (int i = 0; i < 8; i++) {
                    atomicAdd(&d_pooled[cur * H + lane * 8 + i], acc[i]);
                    acc[i] = 0.f;
                }
                cur = b4[k];
            }
            float4 a0 = r[2 * k], a1 = r[2 * k + 1];
            acc[0] += a0.x; acc[1] += a0.y; acc[2] += a0.z; acc[3] += a0.w;
            acc[4] += a1.x; acc[5] += a1.y; acc[6] += a1.z; acc[7] += a1.w;
            dots[k] = a0.x * vr[0] + a0.y * vr[1] + a0.z * vr[2] + a0.w * vr[3]
                    + a1.x * vr[4] + a1.y * vr[5] + a1.z * vr[6] + a1.w * vr[7];
        }
        // 4 independent shfl chains interleave -> latency amortized
#pragma unroll
        for (int o = 16; o > 0; o >>= 1) {
#pragma unroll
            for (int k = 0; k < 4; k++)
                dots[k] += __shfl_xor_sync(0xffffffffu, dots[k], o);
        }
        if (lane == 0) {
#pragma unroll
            for (int k = 0; k < 4; k++) {
                float a = dots[k] + d_qscore[b4[k]];
                a = a > 0.f ? a : 0.2f * a;     // LeakyReLU(0.2)
                if (sel[e + k] == 0) a += 0.5f; // frontier bonus
                d_att_raw[e + k] = a;
            }
        }
    }
    // remainder (<4 edges)
    for (; e < e1; ++e) {
        size_t base = (size_t)e * (H / 4) + lane * 2;
        float4 a0 = row[base], a1 = row[base + 1];
        int b = eb[e];
        if (b != cur) {
#pragma unroll
            for (int i = 0; i < 8; i++) {
                atomicAdd(&d_pooled[cur * H + lane * 8 + i], acc[i]);
                acc[i] = 0.f;
            }
            cur = b;
        }
        acc[0] += a0.x; acc[1] += a0.y; acc[2] += a0.z; acc[3] += a0.w;
        acc[4] += a1.x; acc[5] += a1.y; acc[6] += a1.z; acc[7] += a1.w;
        float p = a0.x * vr[0] + a0.y * vr[1] + a0.z * vr[2] + a0.w * vr[3]
                + a1.x * vr[4] + a1.y * vr[5] + a1.z * vr[6] + a1.w * vr[7];
#pragma unroll
        for (int o = 16; o > 0; o >>= 1) p += __shfl_xor_sync(0xffffffffu, p, o);
        if (lane == 0) {
            float a = p + d_qscore[b];
            a = a > 0.f ? a : 0.2f * a;
            if (sel[e] == 0) a += 0.5f;
            d_att_raw[e] = a;
        }
    }
#pragma unroll
    for (int i = 0; i < 8; i++)
        atomicAdd(&d_pooled[cur * H + lane * 8 + i], acc[i]);
}

// ---------------- block reductions -------------------------------------------
__device__ __forceinline__ float blkRedMax(float v) {
    __shared__ float sm[8];
    int lane = threadIdx.x & 31, w = threadIdx.x >> 5;
#pragma unroll
    for (int o = 16; o > 0; o >>= 1) v = fmaxf(v, __shfl_xor_sync(0xffffffffu, v, o));
    if (lane == 0) sm[w] = v;
    __syncthreads();
    if (w == 0) {
        float t = (lane < 8) ? sm[lane] : -3.402823466e38f;
#pragma unroll
        for (int o = 4; o > 0; o >>= 1) t = fmaxf(t, __shfl_xor_sync(0xffffffffu, t, o));
        if (lane == 0) sm[0] = t;
    }
    __syncthreads();
    float r = sm[0];
    __syncthreads();
    return r;
}
__device__ __forceinline__ float blkRedSum(float v) {
    __shared__ float ss[8];
    int lane = threadIdx.x & 31, w = threadIdx.x >> 5;
#pragma unroll
    for (int o = 16; o > 0; o >>= 1) v += __shfl_xor_sync(0xffffffffu, v, o);
    if (lane == 0) ss[w] = v;
    __syncthreads();
    if (w == 0) {
        float t = (lane < 8) ? ss[lane] : 0.f;
#pragma unroll
        for (int o = 4; o > 0; o >>= 1) t += __shfl_xor_sync(0xffffffffu, t, o);
        if (lane == 0) ss[0] = t;
    }
    __syncthreads();
    float r = ss[0];
    __syncthreads();
    return r;
}

// ---------------- K23: fused segment softmax + logits (block per graph) ------
__global__ void k23_softmax(const int* __restrict__ sel,
                            float* __restrict__ out_edge) {
    int g = blockIdx.x;
    int s = d_bounds[g], eend = d_bounds[g + 1];
    int n = eend - s;
    int t = threadIdx.x;

    float m = -3.402823466e38f;
    for (int i = t; i < n; i += blockDim.x)
        m = fmaxf(m, d_att_raw[s + i]);
    m = blkRedMax(m);

    float sum = 0.f;
    for (int i = t; i < n; i += blockDim.x)
        if (sel[s + i] == 0) sum += expf(d_att_raw[s + i] - m);
    sum = blkRedSum(sum);
    float S = fmaxf(sum, EPS_F);

    for (int i = t; i < n; i += blockDim.x) {
        float p = 0.f;
        if (sel[s + i] == 0) p = expf(d_att_raw[s + i] - m) / S;
        out_edge[s + i] = logf(fmaxf(p, EPS_F));
    }
}

// ---------------- K4: pooled GEMM + stop head (warp-coalesced rows) ----------
__device__ __forceinline__ float blockSum(float v) {
    __shared__ float sb[8];
    int lane = threadIdx.x & 31, w = threadIdx.x >> 5;
#pragma unroll
    for (int o = 16; o > 0; o >>= 1) v += __shfl_xor_sync(0xffffffffu, v, o);
    if (lane == 0) sb[w] = v;
    __syncthreads();
    if (w == 0) {
        float t = (lane < 8) ? sb[lane] : 0.f;
#pragma unroll
        for (int o = 4; o > 0; o >>= 1) t += __shfl_xor_sync(0xffffffffu, t, o);
        if (lane == 0) sb[0] = t;
    }
    __syncthreads();
    float r = sb[0];
    __syncthreads();
    return r;
}

__global__ void k4_head(const float* __restrict__ qt,
                        const float* __restrict__ We,
                        const float* __restrict__ lng,
                        const float* __restrict__ lnb,
                        const float* __restrict__ W1,
                        const float* __restrict__ b1,
                        const float* __restrict__ W2,
                        const float* __restrict__ b2,
                        float* __restrict__ out_stop,
                        float* __restrict__ out_pooled, int G) {
    __shared__ __align__(16) float sS[GPB][H];   // raw-token segment sums
    __shared__ __align__(16) float sIn[GPB][2 * H];
    __shared__ __align__(16) float sXn[GPB][2 * H];
    __shared__ float sH[GPB][H];
    int t = threadIdx.x;
    int lane = t & 31, w = t >> 5;
    int g0 = blockIdx.x * GPB;

    float inv_den[GPB];
#pragma unroll
    for (int gg = 0; gg < GPB; gg++) {
        int g = g0 + gg;
        sS[gg][t] = (g < G) ? d_pooled[g * H + t] : 0.f;
        int cnt = (g < G) ? (d_bounds[g + 1] - d_bounds[g]) : 1;
        inv_den[gg] = 1.f / (float)max(cnt, 1);
    }
    __syncthreads();

    // pooled[g][to] = (sS[g] . We[to,:]) * inv_den  — warp per output row,
    // coalesced We reads (lane covers 8 consecutive floats)
    for (int to = w; to < H; to += 8) {
        const float4* Wr = reinterpret_cast<const float4*>(We + (size_t)to * H);
        float4 w0 = Wr[lane * 2], w1 = Wr[lane * 2 + 1];
        float d[GPB];
#pragma unroll
        for (int gg = 0; gg < GPB; gg++) {
            const float4* sv = reinterpret_cast<const float4*>(&sS[gg][lane * 8]);
            float4 s0 = sv[0], s1 = sv[1];
            d[gg] = s0.x * w0.x + s0.y * w0.y + s0.z * w0.z + s0.w * w0.w
                  + s1.x * w1.x + s1.y * w1.y + s1.z * w1.z + s1.w * w1.w;
        }
#pragma unroll
        for (int o = 16; o > 0; o >>= 1) {
#pragma unroll
            for (int gg = 0; gg < GPB; gg++)
                d[gg] += __shfl_xor_sync(0xffffffffu, d[gg], o);
        }
        if (lane == 0) {
#pragma unroll
            for (int gg = 0; gg < GPB; gg++) {
                int g = g0 + gg;
                float pooled = d[gg] * inv_den[gg];
                sIn[gg][to] = pooled;
                if (g < G) out_pooled[(size_t)g * H + to] = pooled;
            }
        }
    }
#pragma unroll
    for (int gg = 0; gg < GPB; gg++) {
        int g = g0 + gg;
        sIn[gg][t + H] = (g < G) ? qt[(size_t)g * H + t] : 0.f;
    }
    __syncthreads();

    // LayerNorm(2H)
#pragma unroll
    for (int gg = 0; gg < GPB; gg++) {
        float a = sIn[gg][t], b = sIn[gg][t + H];
        float mu = blockSum(a + b) * (1.f / (2.f * H));
        float d0 = a - mu, d1 = b - mu;
        float var = blockSum(d0 * d0 + d1 * d1) * (1.f / (2.f * H));
        float rs = rsqrtf(var + 1e-5f);
        sXn[gg][t] = d0 * rs * lng[t] + lnb[t];
        sXn[gg][t + H] = d1 * rs * lng[t + H] + lnb[t + H];
    }
    __syncthreads();

    // h1[to] = gelu(xn . W1[to,:] + b1[to]) — warp per row, coalesced W1 reads
    for (int to = w; to < H; to += 8) {
        const float4* Wr = reinterpret_cast<const float4*>(W1 + (size_t)to * (2 * H));
        float4 w0 = Wr[lane * 4], w1 = Wr[lane * 4 + 1],
               w2v = Wr[lane * 4 + 2], w3 = Wr[lane * 4 + 3];
        float d[GPB];
#pragma unroll
        for (int gg = 0; gg < GPB; gg++) {
            const float4* xv = reinterpret_cast<const float4*>(&sXn[gg][lane * 16]);
            float4 x0 = xv[0], x1 = xv[1], x2 = xv[2], x3 = xv[3];
            d[gg] = x0.x * w0.x + x0.y * w0.y + x0.z * w0.z + x0.w * w0.w
                  + x1.x * w1.x + x1.y * w1.y + x1.z * w1.z + x1.w * w1.w
                  + x2.x * w2v.x + x2.y * w2v.y + x2.z * w2v.z + x2.w * w2v.w
                  + x3.x * w3.x + x3.y * w3.y + x3.z * w3.z + x3.w * w3.w;
        }
#pragma unroll
        for (int o = 16; o > 0; o >>= 1) {
#pragma unroll
            for (int gg = 0; gg < GPB; gg++)
                d[gg] += __shfl_xor_sync(0xffffffffu, d[gg], o);
        }
        if (lane == 0) {
            float bb = b1[to];
#pragma unroll
            for (int gg = 0; gg < GPB; gg++) {
                float h = d[gg] + bb;
                sH[gg][to] = h * normcdff(h); // exact GELU
            }
        }
    }
    __syncthreads();

    float w2t = W2[t];
#pragma unroll
    for (int gg = 0; gg < GPB; gg++) {
        float s = blockSum(sH[gg][t] * w2t);
        int g = g0 + gg;
        if (t == 0 && g < G) out_stop[g] = s + b2[0];
    }
}

// ---------------- launch -----------------------------------------------------
extern "C" void kernel_launch(void* const* d_in, const int* in_sizes, int n_in,
                              void* d_out, int out_size) {
    const float* et  = (const float*)d_in[0];
    const float* qt  = (const float*)d_in[1];
    const int*   eb  = (const int*)d_in[2];
    const int*   sel = (const int*)d_in[3];
    const float* We  = (const float*)d_in[4];
    const float* Wq  = (const float*)d_in[5];
    const float* av  = (const float*)d_in[6];
    const float* lng = (const float*)d_in[7];
    const float* lnb = (const float*)d_in[8];
    const float* W1  = (const float*)d_in[9];
    const float* b1  = (const float*)d_in[10];
    const float* W2  = (const float*)d_in[11];
    const float* b2  = (const float*)d_in[12];

    int E = in_sizes[2];
    int G = in_sizes[1] / H;
    float* out = (float*)d_out;
    float* out_edge   = out;
    float* out_stop   = out + E;
    float* out_pooled = out + E + G;

    k_init<<<(G * H + 255) / 256, 256>>>(G);
    k_bounds<<<(G + 256) / 256, 256>>>(eb, E, G);
    k0_precompute<<<1, 256>>>(qt, We, Wq, av, G);
    k1_stream<<<296, 256>>>(et, eb, sel, E);
    k23_softmax<<<G, 256>>>(sel, out_edge);
    k4_head<<<(G + GPB - 1) / GPB, 256>>>(qt, We, lng, lnb, W1, b1, W2, b2,
                                          out_stop, out_pooled, G);
}

// round 10
// speedup vs baseline: 2.2609x; 1.8276x over previous
#include <cuda_runtime.h>
#include <cuda_bf16.h>
#include <math.h>

#define H 256
#define E_MAX 500000
#define G_MAX 512
#define EPS_F 1.1920928955078125e-07f
#define GPB 2
#define SMEM_N 6144   // softmax smem cache capacity (edges per graph)

// ---------------- scratch (static device globals) ----------------------------
__device__ float d_att_raw[E_MAX];     // raw dot products (pre-activation)
__device__ float d_v[H];               // att_vec @ W_edge
__device__ float d_w[H];               // att_vec @ W_query
__device__ float d_pooled[G_MAX * H];  // segment_sum of RAW edge_tokens
__device__ int   d_bounds[G_MAX + 1];  // segment boundaries in sorted eb

// ================= kPre: init + bounds + v/w (fused, parallel) ===============
__global__ void k_pre(const int* __restrict__ eb,
                      const float* __restrict__ We,
                      const float* __restrict__ Wq,
                      const float* __restrict__ av,
                      int E, int G, int nInit) {
    int blk = blockIdx.x;
    int t = threadIdx.x;
    if (blk < nInit) {
        int i = blk * 256 + t;
        if (i < G * H) d_pooled[i] = 0.f;
        return;
    }
    if (blk == nInit) {
        for (int g = t; g <= G; g += 256) {
            if (g == G) { d_bounds[G] = E; continue; }
            int lo = 0, hi = E;
            while (lo < hi) {
                int mid = (lo + hi) >> 1;
                if (eb[mid] < g) lo = mid + 1; else hi = mid;
            }
            d_bounds[g] = lo;
        }
        return;
    }
    // v/w matvec: j-th of 8 blocks covers columns [j*32, j*32+32)
    int j = blk - nInit - 1;               // 0..7
    int col = j * 32 + (t & 31);
    int igrp = t >> 5;                      // 0..7, each covers 32 rows
    float v = 0.f, w = 0.f;
    for (int i = igrp * 32; i < igrp * 32 + 32; i++) {
        float a = av[i];
        v += a * We[i * H + col];
        w += a * Wq[i * H + col];
    }
    __shared__ float sv[8][32], sw[8][32];
    sv[igrp][t & 31] = v;
    sw[igrp][t & 31] = w;
    __syncthreads();
    if (igrp == 0) {
        float vs = 0.f, ws = 0.f;
#pragma unroll
        for (int k = 0; k < 8; k++) { vs += sv[k][t & 31]; ws += sw[k][t & 31]; }
        d_v[col] = vs;
        d_w[col] = ws;
    }
}

// ================= K1: heavy streaming pass, 4 edges per iteration ===========
// lane covers h = lane*8 .. lane*8+7; stores RAW dot only (activation deferred)
// __ldcs: edge_tokens is single-use 512MB stream -> evict-first, keep L2 for
// att_raw/pooled/weights
__global__ void __launch_bounds__(256, 3)
k1_stream(const float* __restrict__ et,
          const int* __restrict__ eb, int E) {
    const int lane = threadIdx.x & 31;
    const int wid = blockIdx.x * (blockDim.x >> 5) + (threadIdx.x >> 5);
    const int nw = gridDim.x * (blockDim.x >> 5);
    const int chunk = (E + nw - 1) / nw;
    int e0 = wid * chunk;
    int e1 = min(e0 + chunk, E);
    if (e0 >= e1) return;

    float vr[8];
#pragma unroll
    for (int i = 0; i < 8; i++) vr[i] = d_v[lane * 8 + i];
    float acc[8];
#pragma unroll
    for (int i = 0; i < 8; i++) acc[i] = 0.f;
    int cur = eb[e0];

    const float4* row = reinterpret_cast<const float4*>(et);
    int e = e0;

    for (; e + 4 <= e1; e += 4) {
        float4 r[8];
        size_t base = (size_t)e * (H / 4) + lane * 2;
#pragma unroll
        for (int k = 0; k < 4; k++) {
            r[2 * k]     = __ldcs(&row[base + (size_t)k * (H / 4)]);
            r[2 * k + 1] = __ldcs(&row[base + (size_t)k * (H / 4) + 1]);
        }
        float dots[4];
#pragma unroll
        for (int k = 0; k < 4; k++) {
            int b = eb[e + k];
            if (b != cur) {
#pragma unroll
                for (int i = 0; i < 8; i++) {
                    atomicAdd(&d_pooled[cur * H + lane * 8 + i], acc[i]);
                    acc[i] = 0.f;
                }
                cur = b;
            }
            float4 a0 = r[2 * k], a1 = r[2 * k + 1];
            acc[0] += a0.x; acc[1] += a0.y; acc[2] += a0.z; acc[3] += a0.w;
            acc[4] += a1.x; acc[5] += a1.y; acc[6] += a1.z; acc[7] += a1.w;
            dots[k] = a0.x * vr[0] + a0.y * vr[1] + a0.z * vr[2] + a0.w * vr[3]
                    + a1.x * vr[4] + a1.y * vr[5] + a1.z * vr[6] + a1.w * vr[7];
        }
#pragma unroll
        for (int o = 16; o > 0; o >>= 1) {
#pragma unroll
            for (int k = 0; k < 4; k++)
                dots[k] += __shfl_xor_sync(0xffffffffu, dots[k], o);
        }
        if (lane < 4) d_att_raw[e + lane] = dots[lane];
    }
#pragma unroll 1
    for (; e < e1; ++e) {
        size_t base = (size_t)e * (H / 4) + lane * 2;
        float4 a0 = __ldcs(&row[base]), a1 = __ldcs(&row[base + 1]);
        int b = eb[e];
        if (b != cur) {
#pragma unroll
            for (int i = 0; i < 8; i++) {
                atomicAdd(&d_pooled[cur * H + lane * 8 + i], acc[i]);
                acc[i] = 0.f;
            }
            cur = b;
        }
        acc[0] += a0.x; acc[1] += a0.y; acc[2] += a0.z; acc[3] += a0.w;
        acc[4] += a1.x; acc[5] += a1.y; acc[6] += a1.z; acc[7] += a1.w;
        float p = a0.x * vr[0] + a0.y * vr[1] + a0.z * vr[2] + a0.w * vr[3]
                + a1.x * vr[4] + a1.y * vr[5] + a1.z * vr[6] + a1.w * vr[7];
#pragma unroll
        for (int o = 16; o > 0; o >>= 1) p += __shfl_xor_sync(0xffffffffu, p, o);
        if (lane == 0) d_att_raw[e] = p;
    }
#pragma unroll
    for (int i = 0; i < 8; i++)
        atomicAdd(&d_pooled[cur * H + lane * 8 + i], acc[i]);
}

// ---------------- block reductions -------------------------------------------
__device__ __forceinline__ float blkRedMax(float v) {
    __shared__ float sm[8];
    int lane = threadIdx.x & 31, w = threadIdx.x >> 5;
#pragma unroll
    for (int o = 16; o > 0; o >>= 1) v = fmaxf(v, __shfl_xor_sync(0xffffffffu, v, o));
    if (lane == 0) sm[w] = v;
    __syncthreads();
    if (w == 0) {
        float t = (lane < 8) ? sm[lane] : -3.402823466e38f;
#pragma unroll
        for (int o = 4; o > 0; o >>= 1) t = fmaxf(t, __shfl_xor_sync(0xffffffffu, t, o));
        if (lane == 0) sm[0] = t;
    }
    __syncthreads();
    float r = sm[0];
    __syncthreads();
    return r;
}
__device__ __forceinline__ float blkRedSum(float v) {
    __shared__ float ss[8];
    int lane = threadIdx.x & 31, w = threadIdx.x >> 5;
#pragma unroll
    for (int o = 16; o > 0; o >>= 1) v += __shfl_xor_sync(0xffffffffu, v, o);
    if (lane == 0) ss[w] = v;
    __syncthreads();
    if (w == 0) {
        float t = (lane < 8) ? ss[lane] : 0.f;
#pragma unroll
        for (int o = 4; o > 0; o >>= 1) t += __shfl_xor_sync(0xffffffffu, t, o);
        if (lane == 0) ss[0] = t;
    }
    __syncthreads();
    float r = ss[0];
    __syncthreads();
    return r;
}

// ================= kPost: softmax blocks [0,G) + head blocks [G, G+nh) =======
__device__ __forceinline__ float att_of(float dot, float qs, int s) {
    float a = dot + qs;
    a = a > 0.f ? a : 0.2f * a;            // LeakyReLU(0.2)
    return (s == 0) ? a + 0.5f : a;        // frontier bonus for candidates
}

__device__ void softmax_block(int g, const float* __restrict__ qt,
                              const int* __restrict__ sel,
                              float* __restrict__ out_edge) {
    __shared__ float sa[SMEM_N];
    __shared__ unsigned char scand[SMEM_N];
    int s = d_bounds[g], eend = d_bounds[g + 1];
    int n = eend - s;
    int t = threadIdx.x;

    // qscore = q[g] . d_w
    float qs = blkRedSum(qt[(size_t)g * H + t] * d_w[t]);

    float lEPS = __logf(EPS_F);

    if (n <= SMEM_N) {
        // fast path: single global read of att_raw/sel, rest in smem
        float m = -3.402823466e38f;
        for (int i = t; i < n; i += 256) {
            int sl = sel[s + i];
            float a = att_of(d_att_raw[s + i], qs, sl);
            sa[i] = a;
            scand[i] = (sl == 0) ? 1 : 0;
            m = fmaxf(m, a);
        }
        m = blkRedMax(m);  // also orders sa/scand writes before reuse

        float sum = 0.f;
        for (int i = t; i < n; i += 256)
            if (scand[i]) sum += __expf(sa[i] - m);
        sum = blkRedSum(sum);
        float lS = __logf(fmaxf(sum, EPS_F));

        for (int i = t; i < n; i += 256) {
            float r = scand[i] ? fmaxf(sa[i] - m - lS, lEPS) : lEPS;
            __stcs(&out_edge[s + i], r);
        }
    } else {
        // fallback: identical math, global reads
        float m = -3.402823466e38f;
        for (int i = t; i < n; i += 256)
            m = fmaxf(m, att_of(d_att_raw[s + i], qs, sel[s + i]));
        m = blkRedMax(m);

        float sum = 0.f;
        for (int i = t; i < n; i += 256) {
            int sl = sel[s + i];
            if (sl == 0) sum += __expf(att_of(d_att_raw[s + i], qs, sl) - m);
        }
        sum = blkRedSum(sum);
        float lS = __logf(fmaxf(sum, EPS_F));

        for (int i = t; i < n; i += 256) {
            int sl = sel[s + i];
            float r = (sl == 0)
                ? fmaxf(att_of(d_att_raw[s + i], qs, sl) - m - lS, lEPS)
                : lEPS;
            __stcs(&out_edge[s + i], r);
        }
    }
}

__device__ void head_block(int hb, const float* __restrict__ qt,
                           const float* __restrict__ We,
                           const float* __restrict__ lng,
                           const float* __restrict__ lnb,
                           const float* __restrict__ W1,
                           const float* __restrict__ b1,
                           const float* __restrict__ W2,
                           const float* __restrict__ b2,
                           float* __restrict__ out_stop,
                           float* __restrict__ out_pooled, int G) {
    __shared__ __align__(16) float sS[GPB][H];
    __shared__ __align__(16) float sIn[GPB][2 * H];
    __shared__ __align__(16) float sXn[GPB][2 * H];
    __shared__ float sH[GPB][H];
    int t = threadIdx.x;
    int lane = t & 31, w = t >> 5;
    int g0 = hb * GPB;

    float inv_den[GPB];
#pragma unroll
    for (int gg = 0; gg < GPB; gg++) {
        int g = g0 + gg;
        sS[gg][t] = (g < G) ? d_pooled[g * H + t] : 0.f;
        int cnt = (g < G) ? (d_bounds[g + 1] - d_bounds[g]) : 1;
        inv_den[gg] = 1.f / (float)max(cnt, 1);
    }
    __syncthreads();

    // ---- stage A: pooled = (sS . We-rows) * inv_den, warp per output row ----
    // x cached in registers, chunked layout c*128 + lane*4 -> conflict-free
    {
        float4 xr[GPB][2];
#pragma unroll
        for (int gg = 0; gg < GPB; gg++)
#pragma unroll
            for (int c = 0; c < 2; c++)
                xr[gg][c] = *reinterpret_cast<const float4*>(&sS[gg][c * 128 + lane * 4]);
        for (int to = w; to < H; to += 8) {
            const float* Wr = We + (size_t)to * H;
            float4 w0 = *reinterpret_cast<const float4*>(Wr + lane * 4);
            float4 w1 = *reinterpret_cast<const float4*>(Wr + 128 + lane * 4);
            float d[GPB];
#pragma unroll
            for (int gg = 0; gg < GPB; gg++) {
                float4 a = xr[gg][0], b = xr[gg][1];
                d[gg] = a.x * w0.x + a.y * w0.y + a.z * w0.z + a.w * w0.w
                      + b.x * w1.x + b.y * w1.y + b.z * w1.z + b.w * w1.w;
            }
#pragma unroll
            for (int o = 16; o > 0; o >>= 1)
#pragma unroll
                for (int gg = 0; gg < GPB; gg++)
                    d[gg] += __shfl_xor_sync(0xffffffffu, d[gg], o);
            if (lane == 0) {
#pragma unroll
                for (int gg = 0; gg < GPB; gg++) {
                    int g = g0 + gg;
                    float pooled = d[gg] * inv_den[gg];
                    sIn[gg][to] = pooled;
                    if (g < G) out_pooled[(size_t)g * H + to] = pooled;
                }
            }
        }
    }
#pragma unroll
    for (int gg = 0; gg < GPB; gg++) {
        int g = g0 + gg;
        sIn[gg][t + H] = (g < G) ? qt[(size_t)g * H + t] : 0.f;
    }
    __syncthreads();

    // ---- stage B: LayerNorm(2H) ----
#pragma unroll
    for (int gg = 0; gg < GPB; gg++) {
        float a = sIn[gg][t], b = sIn[gg][t + H];
        float mu = blkRedSum(a + b) * (1.f / (2.f * H));
        float d0 = a - mu, d1 = b - mu;
        float var = blkRedSum(d0 * d0 + d1 * d1) * (1.f / (2.f * H));
        float rs = rsqrtf(var + 1e-5f);
        sXn[gg][t] = d0 * rs * lng[t] + lnb[t];
        sXn[gg][t + H] = d1 * rs * lng[t + H] + lnb[t + H];
    }
    __syncthreads();

    // ---- stage C: h1 = gelu(xn . W1-rows + b1), warp per row, x in regs ----
    {
        float4 xr[GPB][4];
#pragma unroll
        for (int gg = 0; gg < GPB; gg++)
#pragma unroll
            for (int c = 0; c < 4; c++)
                xr[gg][c] = *reinterpret_cast<const float4*>(&sXn[gg][c * 128 + lane * 4]);
        for (int to = w; to < H; to += 8) {
            const float* Wr = W1 + (size_t)to * (2 * H);
            float d[GPB] = {0.f, 0.f};
#pragma unroll
            for (int c = 0; c < 4; c++) {
                float4 wv = *reinterpret_cast<const float4*>(Wr + c * 128 + lane * 4);
#pragma unroll
                for (int gg = 0; gg < GPB; gg++) {
                    float4 a = xr[gg][c];
                    d[gg] += a.x * wv.x + a.y * wv.y + a.z * wv.z + a.w * wv.w;
                }
            }
#pragma unroll
            for (int o = 16; o > 0; o >>= 1)
#pragma unroll
                for (int gg = 0; gg < GPB; gg++)
                    d[gg] += __shfl_xor_sync(0xffffffffu, d[gg], o);
            if (lane == 0) {
                float bb = b1[to];
#pragma unroll
                for (int gg = 0; gg < GPB; gg++) {
                    float h = d[gg] + bb;
                    sH[gg][to] = h * normcdff(h); // exact GELU
                }
            }
        }
    }
    __syncthreads();

    // ---- stage D: stop logits ----
    float w2t = W2[t];
#pragma unroll
    for (int gg = 0; gg < GPB; gg++) {
        float s = blkRedSum(sH[gg][t] * w2t);
        int g = g0 + gg;
        if (t == 0 && g < G) out_stop[g] = s + b2[0];
    }
}

__global__ void k_post(const float* __restrict__ qt,
                       const int* __restrict__ sel,
                       const float* __restrict__ We,
                       const float* __restrict__ lng,
                       const float* __restrict__ lnb,
                       const float* __restrict__ W1,
                       const float* __restrict__ b1,
                       const float* __restrict__ W2,
                       const float* __restrict__ b2,
                       float* __restrict__ out_edge,
                       float* __restrict__ out_stop,
                       float* __restrict__ out_pooled, int G) {
    int blk = blockIdx.x;
    if (blk < G) {
        softmax_block(blk, qt, sel, out_edge);
    } else {
        head_block(blk - G, qt, We, lng, lnb, W1, b1, W2, b2,
                   out_stop, out_pooled, G);
    }
}

// ---------------- launch -----------------------------------------------------
extern "C" void kernel_launch(void* const* d_in, const int* in_sizes, int n_in,
                              void* d_out, int out_size) {
    const float* et  = (const float*)d_in[0];
    const float* qt  = (const float*)d_in[1];
    const int*   eb  = (const int*)d_in[2];
    const int*   sel = (const int*)d_in[3];
    const float* We  = (const float*)d_in[4];
    const float* Wq  = (const float*)d_in[5];
    const float* av  = (const float*)d_in[6];
    const float* lng = (const float*)d_in[7];
    const float* lnb = (const float*)d_in[8];
    const float* W1  = (const float*)d_in[9];
    const float* b1  = (const float*)d_in[10];
    const float* W2  = (const float*)d_in[11];
    const float* b2  = (const float*)d_in[12];

    int E = in_sizes[2];
    int G = in_sizes[1] / H;
    float* out = (float*)d_out;
    float* out_edge   = out;
    float* out_stop   = out + E;
    float* out_pooled = out + E + G;

    int nInit = (G * H + 255) / 256;
    k_pre<<<nInit + 1 + 8, 256>>>(eb, We, Wq, av, E, G, nInit);
    k1_stream<<<444, 256>>>(et, eb, E);
    int nHead = (G + GPB - 1) / GPB;
    k_post<<<G + nHead, 256>>>(qt, sel, We, lng, lnb, W1, b1, W2, b2,
                               out_edge, out_stop, out_pooled, G);
}

// round 16
// speedup vs baseline: 2.2661x; 1.0023x over previous
#include <cuda_runtime.h>
#include <cuda_bf16.h>
#include <math.h>

#define H 256
#define E_MAX 500000
#define G_MAX 512
#define EPS_F 1.1920928955078125e-07f
#define GPB 2
#define SMEM_N 6144   // softmax smem cache capacity (edges per graph)

// ---------------- scratch (static device globals) ----------------------------
__device__ float d_att_raw[E_MAX];     // raw dot products (pre-activation)
__device__ float d_v[H];               // att_vec @ W_edge
__device__ float d_w[H];               // att_vec @ W_query
__device__ float d_pooled[G_MAX * H];  // segment_sum of RAW edge_tokens
__device__ int   d_bounds[G_MAX + 1];  // segment boundaries in sorted eb

// ================= kPre: init + bounds-scan + v/w (fused, parallel) ==========
// blocks [0, nInit): zero d_pooled
// blocks [nInit, nInit+nBound): boundary scatter-scan over sorted eb
//   (coalesced single pass; no dependent-load chains — replaces the binary
//    search that measured 13.5us of pure ptr-chase latency)
// blocks [nInit+nBound, +8): v/w matvec, 32 columns per block
__global__ void k_pre(const int* __restrict__ eb,
                      const float* __restrict__ We,
                      const float* __restrict__ Wq,
                      const float* __restrict__ av,
                      int E, int G, int nInit, int nBound) {
    int blk = blockIdx.x;
    int t = threadIdx.x;
    if (blk < nInit) {
        int i = blk * 256 + t;
        if (i < G * H) d_pooled[i] = 0.f;
        return;
    }
    if (blk < nInit + nBound) {
        int i = (blk - nInit) * 256 + t;
        if (i < E) {
            int b = eb[i];
            int prev = (i == 0) ? -1 : eb[i - 1];
            // d_bounds[g] = first index with eb >= g, for g in (prev, b]
            for (int g = prev + 1; g <= b; g++) d_bounds[g] = i;
            if (i == E - 1) {
                for (int g = b + 1; g <= G; g++) d_bounds[g] = E;
            }
        }
        return;
    }
    // v/w matvec: j-th of 8 blocks covers columns [j*32, j*32+32)
    int j = blk - nInit - nBound;           // 0..7
    int col = j * 32 + (t & 31);
    int igrp = t >> 5;                      // 0..7, each covers 32 rows
    float v = 0.f, w = 0.f;
    for (int i = igrp * 32; i < igrp * 32 + 32; i++) {
        float a = av[i];
        v += a * We[i * H + col];
        w += a * Wq[i * H + col];
    }
    __shared__ float sv[8][32], sw[8][32];
    sv[igrp][t & 31] = v;
    sw[igrp][t & 31] = w;
    __syncthreads();
    if (igrp == 0) {
        float vs = 0.f, ws = 0.f;
#pragma unroll
        for (int k = 0; k < 8; k++) { vs += sv[k][t & 31]; ws += sw[k][t & 31]; }
        d_v[col] = vs;
        d_w[col] = ws;
    }
}

// ================= K1: heavy streaming pass, 4 edges per iteration ===========
// lane covers h = lane*8 .. lane*8+7; stores RAW dot only (activation deferred)
// __ldcs: edge_tokens is single-use 512MB stream -> evict-first, keep L2 for
// att_raw/pooled/weights
__global__ void __launch_bounds__(256, 3)
k1_stream(const float* __restrict__ et,
          const int* __restrict__ eb, int E) {
    const int lane = threadIdx.x & 31;
    const int wid = blockIdx.x * (blockDim.x >> 5) + (threadIdx.x >> 5);
    const int nw = gridDim.x * (blockDim.x >> 5);
    const int chunk = (E + nw - 1) / nw;
    int e0 = wid * chunk;
    int e1 = min(e0 + chunk, E);
    if (e0 >= e1) return;

    float vr[8];
#pragma unroll
    for (int i = 0; i < 8; i++) vr[i] = d_v[lane * 8 + i];
    float acc[8];
#pragma unroll
    for (int i = 0; i < 8; i++) acc[i] = 0.f;
    int cur = eb[e0];

    const float4* row = reinterpret_cast<const float4*>(et);
    int e = e0;

    for (; e + 4 <= e1; e += 4) {
        float4 r[8];
        size_t base = (size_t)e * (H / 4) + lane * 2;
#pragma unroll
        for (int k = 0; k < 4; k++) {
            r[2 * k]     = __ldcs(&row[base + (size_t)k * (H / 4)]);
            r[2 * k + 1] = __ldcs(&row[base + (size_t)k * (H / 4) + 1]);
        }
        float dots[4];
#pragma unroll
        for (int k = 0; k < 4; k++) {
            int b = eb[e + k];
            if (b != cur) {
#pragma unroll
                for (int i = 0; i < 8; i++) {
                    atomicAdd(&d_pooled[cur * H + lane * 8 + i], acc[i]);
                    acc[i] = 0.f;
                }
                cur = b;
            }
            float4 a0 = r[2 * k], a1 = r[2 * k + 1];
            acc[0] += a0.x; acc[1] += a0.y; acc[2] += a0.z; acc[3] += a0.w;
            acc[4] += a1.x; acc[5] += a1.y; acc[6] += a1.z; acc[7] += a1.w;
            dots[k] = a0.x * vr[0] + a0.y * vr[1] + a0.z * vr[2] + a0.w * vr[3]
                    + a1.x * vr[4] + a1.y * vr[5] + a1.z * vr[6] + a1.w * vr[7];
        }
#pragma unroll
        for (int o = 16; o > 0; o >>= 1) {
#pragma unroll
            for (int k = 0; k < 4; k++)
                dots[k] += __shfl_xor_sync(0xffffffffu, dots[k], o);
        }
        if (lane < 4) d_att_raw[e + lane] = dots[lane];
    }
#pragma unroll 1
    for (; e < e1; ++e) {
        size_t base = (size_t)e * (H / 4) + lane * 2;
        float4 a0 = __ldcs(&row[base]), a1 = __ldcs(&row[base + 1]);
        int b = eb[e];
        if (b != cur) {
#pragma unroll
            for (int i = 0; i < 8; i++) {
                atomicAdd(&d_pooled[cur * H + lane * 8 + i], acc[i]);
                acc[i] = 0.f;
            }
            cur = b;
        }
        acc[0] += a0.x; acc[1] += a0.y; acc[2] += a0.z; acc[3] += a0.w;
        acc[4] += a1.x; acc[5] += a1.y; acc[6] += a1.z; acc[7] += a1.w;
        float p = a0.x * vr[0] + a0.y * vr[1] + a0.z * vr[2] + a0.w * vr[3]
                + a1.x * vr[4] + a1.y * vr[5] + a1.z * vr[6] + a1.w * vr[7];
#pragma unroll
        for (int o = 16; o > 0; o >>= 1) p += __shfl_xor_sync(0xffffffffu, p, o);
        if (lane == 0) d_att_raw[e] = p;
    }
#pragma unroll
    for (int i = 0; i < 8; i++)
        atomicAdd(&d_pooled[cur * H + lane * 8 + i], acc[i]);
}

// ---------------- block reductions -------------------------------------------
__device__ __forceinline__ float blkRedMax(float v) {
    __shared__ float sm[8];
    int lane = threadIdx.x & 31, w = threadIdx.x >> 5;
#pragma unroll
    for (int o = 16; o > 0; o >>= 1) v = fmaxf(v, __shfl_xor_sync(0xffffffffu, v, o));
    if (lane == 0) sm[w] = v;
    __syncthreads();
    if (w == 0) {
        float t = (lane < 8) ? sm[lane] : -3.402823466e38f;
#pragma unroll
        for (int o = 4; o > 0; o >>= 1) t = fmaxf(t, __shfl_xor_sync(0xffffffffu, t, o));
        if (lane == 0) sm[0] = t;
    }
    __syncthreads();
    float r = sm[0];
    __syncthreads();
    return r;
}
__device__ __forceinline__ float blkRedSum(float v) {
    __shared__ float ss[8];
    int lane = threadIdx.x & 31, w = threadIdx.x >> 5;
#pragma unroll
    for (int o = 16; o > 0; o >>= 1) v += __shfl_xor_sync(0xffffffffu, v, o);
    if (lane == 0) ss[w] = v;
    __syncthreads();
    if (w == 0) {
        float t = (lane < 8) ? ss[lane] : 0.f;
#pragma unroll
        for (int o = 4; o > 0; o >>= 1) t += __shfl_xor_sync(0xffffffffu, t, o);
        if (lane == 0) ss[0] = t;
    }
    __syncthreads();
    float r = ss[0];
    __syncthreads();
    return r;
}

// ================= kPost: softmax blocks [0,G) + head blocks [G, G+nh) =======
__device__ __forceinline__ float att_of(float dot, float qs, int s) {
    float a = dot + qs;
    a = a > 0.f ? a : 0.2f * a;            // LeakyReLU(0.2)
    return (s == 0) ? a + 0.5f : a;        // frontier bonus for candidates
}

__device__ void softmax_block(int g, const float* __restrict__ qt,
                              const int* __restrict__ sel,
                              float* __restrict__ out_edge) {
    __shared__ float sa[SMEM_N];
    __shared__ unsigned char scand[SMEM_N];
    int s = d_bounds[g], eend = d_bounds[g + 1];
    int n = eend - s;
    int t = threadIdx.x;

    // qscore = q[g] . d_w
    float qs = blkRedSum(qt[(size_t)g * H + t] * d_w[t]);

    float lEPS = __logf(EPS_F);

    if (n <= SMEM_N) {
        // fast path: single global read of att_raw/sel, rest in smem
        float m = -3.402823466e38f;
        for (int i = t; i < n; i += 256) {
            int sl = sel[s + i];
            float a = att_of(d_att_raw[s + i], qs, sl);
            sa[i] = a;
            scand[i] = (sl == 0) ? 1 : 0;
            m = fmaxf(m, a);
        }
        m = blkRedMax(m);  // also orders sa/scand writes before reuse

        float sum = 0.f;
        for (int i = t; i < n; i += 256)
            if (scand[i]) sum += __expf(sa[i] - m);
        sum = blkRedSum(sum);
        float lS = __logf(fmaxf(sum, EPS_F));

        for (int i = t; i < n; i += 256) {
            float r = scand[i] ? fmaxf(sa[i] - m - lS, lEPS) : lEPS;
            __stcs(&out_edge[s + i], r);
        }
    } else {
        // fallback: identical math, global reads
        float m = -3.402823466e38f;
        for (int i = t; i < n; i += 256)
            m = fmaxf(m, att_of(d_att_raw[s + i], qs, sel[s + i]));
        m = blkRedMax(m);

        float sum = 0.f;
        for (int i = t; i < n; i += 256) {
            int sl = sel[s + i];
            if (sl == 0) sum += __expf(att_of(d_att_raw[s + i], qs, sl) - m);
        }
        sum = blkRedSum(sum);
        float lS = __logf(fmaxf(sum, EPS_F));

        for (int i = t; i < n; i += 256) {
            int sl = sel[s + i];
            float r = (sl == 0)
                ? fmaxf(att_of(d_att_raw[s + i], qs, sl) - m - lS, lEPS)
                : lEPS;
            __stcs(&out_edge[s + i], r);
        }
    }
}

__device__ void head_block(int hb, const float* __restrict__ qt,
                           const float* __restrict__ We,
                           const float* __restrict__ lng,
                           const float* __restrict__ lnb,
                           const float* __restrict__ W1,
                           const float* __restrict__ b1,
                           const float* __restrict__ W2,
                           const float* __restrict__ b2,
                           float* __restrict__ out_stop,
                           float* __restrict__ out_pooled, int G) {
    __shared__ __align__(16) float sS[GPB][H];
    __shared__ __align__(16) float sIn[GPB][2 * H];
    __shared__ __align__(16) float sXn[GPB][2 * H];
    __shared__ float sH[GPB][H];
    int t = threadIdx.x;
    int lane = t & 31, w = t >> 5;
    int g0 = hb * GPB;

    float inv_den[GPB];
#pragma unroll
    for (int gg = 0; gg < GPB; gg++) {
        int g = g0 + gg;
        sS[gg][t] = (g < G) ? d_pooled[g * H + t] : 0.f;
        int cnt = (g < G) ? (d_bounds[g + 1] - d_bounds[g]) : 1;
        inv_den[gg] = 1.f / (float)max(cnt, 1);
    }
    __syncthreads();

    // ---- stage A: pooled = (sS . We-rows) * inv_den, warp per output row ----
    // x cached in registers, chunked layout c*128 + lane*4 -> conflict-free
    {
        float4 xr[GPB][2];
#pragma unroll
        for (int gg = 0; gg < GPB; gg++)
#pragma unroll
            for (int c = 0; c < 2; c++)
                xr[gg][c] = *reinterpret_cast<const float4*>(&sS[gg][c * 128 + lane * 4]);
        for (int to = w; to < H; to += 8) {
            const float* Wr = We + (size_t)to * H;
            float4 w0 = *reinterpret_cast<const float4*>(Wr + lane * 4);
            float4 w1 = *reinterpret_cast<const float4*>(Wr + 128 + lane * 4);
            float d[GPB];
#pragma unroll
            for (int gg = 0; gg < GPB; gg++) {
                float4 a = xr[gg][0], b = xr[gg][1];
                d[gg] = a.x * w0.x + a.y * w0.y + a.z * w0.z + a.w * w0.w
                      + b.x * w1.x + b.y * w1.y + b.z * w1.z + b.w * w1.w;
            }
#pragma unroll
            for (int o = 16; o > 0; o >>= 1)
#pragma unroll
                for (int gg = 0; gg < GPB; gg++)
                    d[gg] += __shfl_xor_sync(0xffffffffu, d[gg], o);
            if (lane == 0) {
#pragma unroll
                for (int gg = 0; gg < GPB; gg++) {
                    int g = g0 + gg;
                    float pooled = d[gg] * inv_den[gg];
                    sIn[gg][to] = pooled;
                    if (g < G) out_pooled[(size_t)g * H + to] = pooled;
                }
            }
        }
    }
#pragma unroll
    for (int gg = 0; gg < GPB; gg++) {
        int g = g0 + gg;
        sIn[gg][t + H] = (g < G) ? qt[(size_t)g * H + t] : 0.f;
    }
    __syncthreads();

    // ---- stage B: LayerNorm(2H) ----
#pragma unroll
    for (int gg = 0; gg < GPB; gg++) {
        float a = sIn[gg][t], b = sIn[gg][t + H];
        float mu = blkRedSum(a + b) * (1.f / (2.f * H));
        float d0 = a - mu, d1 = b - mu;
        float var = blkRedSum(d0 * d0 + d1 * d1) * (1.f / (2.f * H));
        float rs = rsqrtf(var + 1e-5f);
        sXn[gg][t] = d0 * rs * lng[t] + lnb[t];
        sXn[gg][t + H] = d1 * rs * lng[t + H] + lnb[t + H];
    }
    __syncthreads();

    // ---- stage C: h1 = gelu(xn . W1-rows + b1), warp per row, x in regs ----
    {
        float4 xr[GPB][4];
#pragma unroll
        for (int gg = 0; gg < GPB; gg++)
#pragma unroll
            for (int c = 0; c < 4; c++)
                xr[gg][c] = *reinterpret_cast<const float4*>(&sXn[gg][c * 128 + lane * 4]);
        for (int to = w; to < H; to += 8) {
            const float* Wr = W1 + (size_t)to * (2 * H);
            float d[GPB] = {0.f, 0.f};
#pragma unroll
            for (int c = 0; c < 4; c++) {
                float4 wv = *reinterpret_cast<const float4*>(Wr + c * 128 + lane * 4);
#pragma unroll
                for (int gg = 0; gg < GPB; gg++) {
                    float4 a = xr[gg][c];
                    d[gg] += a.x * wv.x + a.y * wv.y + a.z * wv.z + a.w * wv.w;
                }
            }
#pragma unroll
            for (int o = 16; o > 0; o >>= 1)
#pragma unroll
                for (int gg = 0; gg < GPB; gg++)
                    d[gg] += __shfl_xor_sync(0xffffffffu, d[gg], o);
            if (lane == 0) {
                float bb = b1[to];
#pragma unroll
                for (int gg = 0; gg < GPB; gg++) {
                    float h = d[gg] + bb;
                    sH[gg][to] = h * normcdff(h); // exact GELU
                }
            }
        }
    }
    __syncthreads();

    // ---- stage D: stop logits ----
    float w2t = W2[t];
#pragma unroll
    for (int gg = 0; gg < GPB; gg++) {
        float s = blkRedSum(sH[gg][t] * w2t);
        int g = g0 + gg;
        if (t == 0 && g < G) out_stop[g] = s + b2[0];
    }
}

__global__ void k_post(const float* __restrict__ qt,
                       const int* __restrict__ sel,
                       const float* __restrict__ We,
                       const float* __restrict__ lng,
                       const float* __restrict__ lnb,
                       const float* __restrict__ W1,
                       const float* __restrict__ b1,
                       const float* __restrict__ W2,
                       const float* __restrict__ b2,
                       float* __restrict__ out_edge,
                       float* __restrict__ out_stop,
                       float* __restrict__ out_pooled, int G) {
    int blk = blockIdx.x;
    if (blk < G) {
        softmax_block(blk, qt, sel, out_edge);
    } else {
        head_block(blk - G, qt, We, lng, lnb, W1, b1, W2, b2,
                   out_stop, out_pooled, G);
    }
}

// ---------------- launch -----------------------------------------------------
extern "C" void kernel_launch(void* const* d_in, const int* in_sizes, int n_in,
                              void* d_out, int out_size) {
    const float* et  = (const float*)d_in[0];
    const float* qt  = (const float*)d_in[1];
    const int*   eb  = (const int*)d_in[2];
    const int*   sel = (const int*)d_in[3];
    const float* We  = (const float*)d_in[4];
    const float* Wq  = (const float*)d_in[5];
    const float* av  = (const float*)d_in[6];
    const float* lng = (const float*)d_in[7];
    const float* lnb = (const float*)d_in[8];
    const float* W1  = (const float*)d_in[9];
    const float* b1  = (const float*)d_in[10];
    const float* W2  = (const float*)d_in[11];
    const float* b2  = (const float*)d_in[12];

    int E = in_sizes[2];
    int G = in_sizes[1] / H;
    float* out = (float*)d_out;
    float* out_edge   = out;
    float* out_stop   = out + E;
    float* out_pooled = out + E + G;

    int nInit = (G * H + 255) / 256;
    int nBound = (E + 255) / 256;
    k_pre<<<nInit + nBound + 8, 256>>>(eb, We, Wq, av, E, G, nInit, nBound);
    k1_stream<<<444, 256>>>(et, eb, E);
    int nHead = (G + GPB - 1) / GPB;
    k_post<<<G + nHead, 256>>>(qt, sel, We, lng, lnb, W1, b1, W2, b2,
                               out_edge, out_stop, out_pooled, G);
}